// round 14
// baseline (speedup 1.0000x reference)
#include <cuda_runtime.h>
#include <cuda_bf16.h>
#include <cstdint>
#include <math.h>

#define BATCH 8
#define CIN 512
#define SEQT 2048
#define DF 512
#define NH 8
#define DH 64
#define MROWS (BATCH*SEQT)   // 16384

// Scratch (allocation-free rule: __device__ globals)
__device__ __nv_bfloat16 g_hn  [MROWS * DF];          // LN output
__device__ __nv_bfloat16 g_qkv [MROWS * 3 * DF];      // fused q|k|v, row stride 1536
__device__ __nv_bfloat16 g_ctx [MROWS * DF];
__device__ __nv_bfloat16 g_wqkv[CIN * 3 * DF];        // packed bf16 weights [512][1536]
__device__ __nv_bfloat16 g_wo  [CIN * DF];
__device__ float         g_bqkv[3 * DF];

// ===========================================================================
// helpers
// ===========================================================================
__device__ __forceinline__ uint32_t pk(float lo, float hi) {
    uint32_t d;
    asm("cvt.rn.bf16x2.f32 %0, %1, %2;" : "=r"(d) : "f"(hi), "f"(lo));
    return d;
}
__device__ __forceinline__ uint32_t ex2b(uint32_t x) {   // two exp2 per MUFU op
    uint32_t y;
    asm("ex2.approx.ftz.bf16x2 %0, %1;" : "=r"(y) : "r"(x));
    return y;
}
__device__ __forceinline__ void mma16(float* d, const uint32_t* a, const uint32_t* b) {
    asm volatile(
        "mma.sync.aligned.m16n8k16.row.col.f32.bf16.bf16.f32 "
        "{%0,%1,%2,%3}, {%4,%5,%6,%7}, {%8,%9}, {%0,%1,%2,%3};"
        : "+f"(d[0]), "+f"(d[1]), "+f"(d[2]), "+f"(d[3])
        : "r"(a[0]), "r"(a[1]), "r"(a[2]), "r"(a[3]), "r"(b[0]), "r"(b[1]));
}
__device__ __forceinline__ void ldsm4(uint32_t* r, uint32_t a) {
    asm volatile("ldmatrix.sync.aligned.m8n8.x4.shared.b16 {%0,%1,%2,%3}, [%4];"
        : "=r"(r[0]), "=r"(r[1]), "=r"(r[2]), "=r"(r[3]) : "r"(a));
}
__device__ __forceinline__ void ldsm4t(uint32_t* r, uint32_t a) {
    asm volatile("ldmatrix.sync.aligned.m8n8.x4.trans.shared.b16 {%0,%1,%2,%3}, [%4];"
        : "=r"(r[0]), "=r"(r[1]), "=r"(r[2]), "=r"(r[3]) : "r"(a));
}
__device__ __forceinline__ void cp16(uint32_t saddr, const void* g) {
    asm volatile("cp.async.cg.shared.global [%0], [%1], 16;" :: "r"(saddr), "l"(g));
}
#define CP_COMMIT() asm volatile("cp.async.commit_group;" ::: "memory")
#define CP_WAIT1()  asm volatile("cp.async.wait_group 1;" ::: "memory")
#define CP_WAIT0()  asm volatile("cp.async.wait_group 0;" ::: "memory")
__device__ __forceinline__ uint32_t smem_u32(const void* p) {
    uint32_t a;
    asm("{ .reg .u64 t; cvta.to.shared.u64 t, %1; cvt.u32.u64 %0, t; }" : "=r"(a) : "l"(p));
    return a;
}

// ===========================================================================
// LayerNorm: x (B, C, T) -> hn (B*T, C) bf16.  SINGLE PASS, x read once:
// 512 threads, 32 t-columns per CTA, 32 fp32 values per thread in registers.
// Phase A: coalesced read + per-thread partial sums.
// Phase B: cross-c-lane reduction (16 lanes) in smem.
// Phase C: normalize from registers through a 32x33 transpose tile -> bf16.
// ===========================================================================
__global__ __launch_bounds__(512, 2)
void ln_kernel(const float* __restrict__ x, const float* __restrict__ gamma,
               const float* __restrict__ beta, __nv_bfloat16* __restrict__ hn) {
    int b = blockIdx.y, t0 = blockIdx.x * 32;
    int tid = threadIdx.x;
    int tx = tid & 31, cy = tid >> 5;   // 16 c-lanes
    const float* xp = x + (size_t)b * CIN * SEQT + t0;
    float vals[32];
    float s = 0.f, s2 = 0.f;
#pragma unroll
    for (int i = 0; i < 32; i++) {
        int c = cy + i * 16;
        float v = xp[(size_t)c * SEQT + tx];
        vals[i] = v; s += v; s2 += v * v;
    }
    __shared__ float ss[16][32], ss2[16][32], mean_s[32], rstd_s[32];
    ss[cy][tx] = s; ss2[cy][tx] = s2;
    __syncthreads();
    if (cy == 0) {
        float S = 0.f, S2 = 0.f;
#pragma unroll
        for (int i = 0; i < 16; i++) { S += ss[i][tx]; S2 += ss2[i][tx]; }
        float mean = S * (1.f / CIN);
        float var = S2 * (1.f / CIN) - mean * mean;
        mean_s[tx] = mean;
        rstd_s[tx] = rsqrtf(var + 1e-5f);
    }
    __syncthreads();
    float mean = mean_s[tx], rstd = rstd_s[tx];
    __shared__ float tile[32][33];
#pragma unroll 1
    for (int c0 = 0; c0 < CIN; c0 += 32) {
        int i0 = c0 >> 4;
        // this thread owns c = c0 + cy (vals[i0]) and c = c0 + 16 + cy (vals[i0+1])
        tile[cy][tx]      = (vals[i0]     - mean) * rstd * gamma[c0 + cy]      + beta[c0 + cy];
        tile[cy + 16][tx] = (vals[i0 + 1] - mean) * rstd * gamma[c0 + 16 + cy] + beta[c0 + 16 + cy];
        __syncthreads();
        // write 32t x 32c chunk: lanes sweep consecutive c for coalescing
#pragma unroll
        for (int k = 0; k < 2; k++) {
            int e = tid + k * 512;
            int cc = e & 31, t = e >> 5;
            hn[(size_t)(b * SEQT + t0 + t) * CIN + c0 + cc] = __float2bfloat16(tile[cc][t]);
        }
        __syncthreads();
    }
}

// ===========================================================================
// single pack/convert: wq|wk|wv -> wqkv[512][1536] bf16, wo -> bf16,
// bq|bk|bv -> bqkv[1536] fp32
// ===========================================================================
__global__ void cvt_pack(const float* __restrict__ wq, const float* __restrict__ wk,
                         const float* __restrict__ wv, const float* __restrict__ wo,
                         const float* __restrict__ bq, const float* __restrict__ bk,
                         const float* __restrict__ bv,
                         __nv_bfloat16* __restrict__ wqkv, __nv_bfloat16* __restrict__ wob,
                         float* __restrict__ bqkv) {
    int t = blockIdx.x * 256 + threadIdx.x;
    int i = t * 4;                       // over 4*512*512 = 1M floats
    int w = i >> 18;                     // which weight
    int r = i & 0x3FFFF;
    const float* src = (w == 0) ? wq : (w == 1) ? wk : (w == 2) ? wv : wo;
    float4 v = *(const float4*)(src + r);
    uint2 p = {pk(v.x, v.y), pk(v.z, v.w)};
    if (w < 3) {
        int kk = r >> 9, n = r & 511;
        *(uint2*)(wqkv + (size_t)kk * 1536 + w * 512 + n) = p;
    } else {
        *(uint2*)(wob + r) = p;
    }
    if (t < 3 * DF)
        bqkv[t] = (t < 512) ? bq[t] : (t < 1024) ? bk[t - 512] : bv[t - 1024];
}

// ===========================================================================
// fused QKV GEMM: qkv[M,1536] = hn[M,512] @ wqkv[512,1536] + bqkv
// 128x128 tile, BK=64, 256 thr. 3-stage cp.async, ONE barrier per k-tile.
// Epilogue staged through smem for fully coalesced 16B global stores.
// ===========================================================================
#define GA_SZ 16384
#define GB_SZ 16384
#define GBUF  (GA_SZ + GB_SZ)
#define GEMM_SMEM (3 * GBUF)   // 98304
#define CST 68                  // staging row stride in 32-bit words (conflict-free)

__global__ __launch_bounds__(256, 2)
void gemm_qkv(const __nv_bfloat16* __restrict__ A, const __nv_bfloat16* __restrict__ W,
              const float* __restrict__ bias, __nv_bfloat16* __restrict__ C) {
    extern __shared__ char sm[];
    uint32_t sb = smem_u32(sm);
    const int tid = threadIdx.x;
    const int wid = tid >> 5, lane = tid & 31;
    const int g = lane >> 2, tg = lane & 3;
    const int bm = blockIdx.y * 128, bn = blockIdx.x * 128;
    const int wm = (wid & 3) * 32, wn = (wid >> 2) * 64;
    const float scale = (bn < 512) ? 0.125f * 1.44269504088896f : 1.0f;

#define G_ISSUE(kt, buf) do {                                                        \
        uint32_t base_ = sb + (uint32_t)(buf) * GBUF;                                \
        _Pragma("unroll")                                                            \
        for (int i_ = 0; i_ < 4; i_++) {                                             \
            int idx = tid + i_ * 256;                                                \
            int r = idx >> 3, c = idx & 7;                                           \
            cp16(base_ + r * 128 + ((c ^ (r & 7)) << 4),                             \
                 A + (size_t)(bm + r) * 512 + (kt) * 64 + c * 8);                    \
        }                                                                            \
        _Pragma("unroll")                                                            \
        for (int i_ = 0; i_ < 4; i_++) {                                             \
            int idx = tid + i_ * 256;                                                \
            int r = idx >> 4, c = idx & 15;                                          \
            cp16(base_ + GA_SZ + r * 256 + ((c ^ (r & 7)) << 4),                     \
                 W + (size_t)((kt) * 64 + r) * 1536 + bn + c * 8);                   \
        }                                                                            \
        CP_COMMIT();                                                                 \
    } while (0)

    float acc[2][8][4];
#pragma unroll
    for (int mt = 0; mt < 2; mt++)
#pragma unroll
        for (int nt = 0; nt < 8; nt++)
#pragma unroll
            for (int j = 0; j < 4; j++) acc[mt][nt][j] = 0.f;

    G_ISSUE(0, 0);
    G_ISSUE(1, 1);
    int br = 0;
    for (int kt = 0; kt < 8; kt++) {
        if (kt < 7) CP_WAIT1(); else CP_WAIT0();
        __syncthreads();
        if (kt + 2 < 8) {
            int bi = br + 2; if (bi >= 3) bi -= 3;
            G_ISSUE(kt + 2, bi);
        }
        uint32_t base = sb + br * GBUF;
#pragma unroll
        for (int ks = 0; ks < 4; ks++) {
            uint32_t a[2][4];
#pragma unroll
            for (int mt = 0; mt < 2; mt++) {
                int row = wm + mt * 16 + (lane & 7) + ((lane & 8) ? 8 : 0);
                int c = ks * 2 + ((lane >> 4) & 1);
                ldsm4(a[mt], base + row * 128 + ((c ^ (row & 7)) << 4));
            }
            uint32_t bb[4][4];
#pragma unroll
            for (int j = 0; j < 4; j++) {
                int krow = ks * 16 + (lane & 7) + ((lane & 8) ? 8 : 0);
                int c = ((wn + j * 16) >> 3) + ((lane >> 4) & 1);
                ldsm4t(bb[j], base + GA_SZ + krow * 256 + ((c ^ (krow & 7)) << 4));
            }
#pragma unroll
            for (int mt = 0; mt < 2; mt++)
#pragma unroll
                for (int j = 0; j < 4; j++) {
                    mma16(acc[mt][2 * j], a[mt], &bb[j][0]);
                    mma16(acc[mt][2 * j + 1], a[mt], &bb[j][2]);
                }
        }
        if (++br == 3) br = 0;
    }

    // epilogue: stage bf16 C tile in smem (stride CST words), then coalesced
    // STG.128 stores (warp = 2 rows x 256B contiguous).
    __syncthreads();
    uint32_t* cs = (uint32_t*)sm;
#pragma unroll
    for (int mt = 0; mt < 2; mt++) {
        int r0 = wm + mt * 16 + g;
#pragma unroll
        for (int nt = 0; nt < 8; nt++) {
            int col = wn + nt * 8 + 2 * tg;
            float b0 = bias[bn + col], b1 = bias[bn + col + 1];
            cs[r0 * CST + (col >> 1)] =
                pk((acc[mt][nt][0] + b0) * scale, (acc[mt][nt][1] + b1) * scale);
            cs[(r0 + 8) * CST + (col >> 1)] =
                pk((acc[mt][nt][2] + b0) * scale, (acc[mt][nt][3] + b1) * scale);
        }
    }
    __syncthreads();
    uint32_t* Cw = (uint32_t*)C;
#pragma unroll
    for (int i = 0; i < 8; i++) {
        int f = tid + i * 256;          // 2048 16B-chunks: 128 rows x 16
        int r = f >> 4, c4 = (f & 15) << 2;
        uint4 v = *(uint4*)(cs + r * CST + c4);
        *(uint4*)(Cw + (size_t)(bm + r) * 768 + (bn >> 1) + c4) = v;
    }
#undef G_ISSUE
}

// ===========================================================================
// output GEMM + residual + transpose: out[b][c][t] = x[b][c][t] +
//   (ctx[b*T+t][:] @ wo)[c] + bo[c].  3-stage, one barrier per k-tile.
// ===========================================================================
__global__ __launch_bounds__(256, 2)
void gemm_out(const __nv_bfloat16* __restrict__ A, const __nv_bfloat16* __restrict__ W,
              const float* __restrict__ bias, const float* __restrict__ x,
              float* __restrict__ out) {
    extern __shared__ char sm[];
    uint32_t sb = smem_u32(sm);
    const int tid = threadIdx.x;
    const int wid = tid >> 5, lane = tid & 31;
    const int g = lane >> 2, tg = lane & 3;
    const int bm = blockIdx.y * 128, bn = blockIdx.x * 128;
    const int wm = (wid & 3) * 32, wn = (wid >> 2) * 64;

#define G_ISSUE(kt, buf) do {                                                        \
        uint32_t base_ = sb + (uint32_t)(buf) * GBUF;                                \
        _Pragma("unroll")                                                            \
        for (int i_ = 0; i_ < 4; i_++) {                                             \
            int idx = tid + i_ * 256;                                                \
            int r = idx >> 3, c = idx & 7;                                           \
            cp16(base_ + r * 128 + ((c ^ (r & 7)) << 4),                             \
                 A + (size_t)(bm + r) * 512 + (kt) * 64 + c * 8);                    \
        }                                                                            \
        _Pragma("unroll")                                                            \
        for (int i_ = 0; i_ < 4; i_++) {                                             \
            int idx = tid + i_ * 256;                                                \
            int r = idx >> 4, c = idx & 15;                                          \
            cp16(base_ + GA_SZ + r * 256 + ((c ^ (r & 7)) << 4),                     \
                 W + (size_t)((kt) * 64 + r) * 512 + bn + c * 8);                    \
        }                                                                            \
        CP_COMMIT();                                                                 \
    } while (0)

    float acc[2][8][4];
#pragma unroll
    for (int mt = 0; mt < 2; mt++)
#pragma unroll
        for (int nt = 0; nt < 8; nt++)
#pragma unroll
            for (int j = 0; j < 4; j++) acc[mt][nt][j] = 0.f;

    G_ISSUE(0, 0);
    G_ISSUE(1, 1);
    int br = 0;
    for (int kt = 0; kt < 8; kt++) {
        if (kt < 7) CP_WAIT1(); else CP_WAIT0();
        __syncthreads();
        if (kt + 2 < 8) {
            int bi = br + 2; if (bi >= 3) bi -= 3;
            G_ISSUE(kt + 2, bi);
        }
        uint32_t base = sb + br * GBUF;
#pragma unroll
        for (int ks = 0; ks < 4; ks++) {
            uint32_t a[2][4];
#pragma unroll
            for (int mt = 0; mt < 2; mt++) {
                int row = wm + mt * 16 + (lane & 7) + ((lane & 8) ? 8 : 0);
                int c = ks * 2 + ((lane >> 4) & 1);
                ldsm4(a[mt], base + row * 128 + ((c ^ (row & 7)) << 4));
            }
            uint32_t bb[4][4];
#pragma unroll
            for (int j = 0; j < 4; j++) {
                int krow = ks * 16 + (lane & 7) + ((lane & 8) ? 8 : 0);
                int c = ((wn + j * 16) >> 3) + ((lane >> 4) & 1);
                ldsm4t(bb[j], base + GA_SZ + krow * 256 + ((c ^ (krow & 7)) << 4));
            }
#pragma unroll
            for (int mt = 0; mt < 2; mt++)
#pragma unroll
                for (int j = 0; j < 4; j++) {
                    mma16(acc[mt][2 * j], a[mt], &bb[j][0]);
                    mma16(acc[mt][2 * j + 1], a[mt], &bb[j][2]);
                }
        }
        if (++br == 3) br = 0;
    }

    // epilogue: transpose + residual. row=(b,t), col=c -> out[((b*512+c)*2048)+t]
#pragma unroll
    for (int mt = 0; mt < 2; mt++) {
        int row = bm + wm + mt * 16 + g;
        int bI = row >> 11, t = row & 2047;
#pragma unroll
        for (int nt = 0; nt < 8; nt++) {
            int col = bn + wn + nt * 8 + 2 * tg;
            float b0 = bias[col], b1 = bias[col + 1];
            size_t i00 = ((size_t)(bI * 512 + col)) * 2048 + t;
            size_t i10 = i00 + 2048;             // col+1
            out[i00]     = x[i00]     + acc[mt][nt][0] + b0;
            out[i10]     = x[i10]     + acc[mt][nt][1] + b1;
            out[i00 + 8] = x[i00 + 8] + acc[mt][nt][2] + b0;   // row+8 -> t+8
            out[i10 + 8] = x[i10 + 8] + acc[mt][nt][3] + b1;
        }
    }
#undef G_ISSUE
}

// ===========================================================================
// Flash attention, causal, bf16 mma, qkv packed (row stride 1536).
// NO-MAX softmax, exp2 via bf16x2 MUFU (2 exps/op), denominator via
// ones-MMA (l = P @ 1) on the tensor pipe — measured-best configuration.
// 3-stage KV pipeline, one barrier per tile.
// ===========================================================================
#define FQ_SZ 16384
#define FKV_SZ 16384
#define FLASH_SMEM (FQ_SZ + 3 * FKV_SZ)   // 65536
#define QKV_ST 1536

__global__ __launch_bounds__(256, 2)
void flash_bf16(const __nv_bfloat16* __restrict__ qkv, __nv_bfloat16* __restrict__ ctx) {
    extern __shared__ char sm[];
    uint32_t sb = smem_u32(sm);
    const int qt = (int)(gridDim.x - 1 - blockIdx.x);   // heavy tiles first
    const int bh = blockIdx.y;
    const int b = bh >> 3, h = bh & 7;
    const int qb = qt * 128;
    const int tid = threadIdx.x, wid = tid >> 5, lane = tid & 31;
    const int g = lane >> 2, tg = lane & 3;
    const int rowbase = qb + wid * 16;
    const int ktmax = 2 * qt + 2;

    const __nv_bfloat16* qp  = qkv + (size_t)(b * SEQT + qb) * QKV_ST + h * 64;
    const __nv_bfloat16* kb0 = qkv + (size_t)b * SEQT * QKV_ST + 512 + h * 64;
    const __nv_bfloat16* vb0 = qkv + (size_t)b * SEQT * QKV_ST + 1024 + h * 64;

#define F_ISSUE(kt, buf) do {                                                        \
        uint32_t base_ = sb + FQ_SZ + (uint32_t)(buf) * FKV_SZ;                      \
        const __nv_bfloat16* kp_ = kb0 + (size_t)(kt) * 64 * QKV_ST;                 \
        const __nv_bfloat16* vp_ = vb0 + (size_t)(kt) * 64 * QKV_ST;                 \
        _Pragma("unroll")                                                            \
        for (int i_ = 0; i_ < 2; i_++) {                                             \
            int idx = tid + i_ * 256;                                                \
            int r = idx >> 3, c = idx & 7;                                           \
            uint32_t off = r * 128 + ((c ^ (r & 7)) << 4);                           \
            cp16(base_ + off, kp_ + (size_t)r * QKV_ST + c * 8);                     \
            cp16(base_ + 8192 + off, vp_ + (size_t)r * QKV_ST + c * 8);              \
        }                                                                            \
        CP_COMMIT();                                                                 \
    } while (0)

    // group 0: Q + KV(0); group 1: KV(1)
#pragma unroll
    for (int i = 0; i < 4; i++) {
        int idx = tid + i * 256;
        int r = idx >> 3, c = idx & 7;
        cp16(sb + r * 128 + ((c ^ (r & 7)) << 4), qp + (size_t)r * QKV_ST + c * 8);
    }
    {
        uint32_t base_ = sb + FQ_SZ;
#pragma unroll
        for (int i = 0; i < 2; i++) {
            int idx = tid + i * 256;
            int r = idx >> 3, c = idx & 7;
            uint32_t off = r * 128 + ((c ^ (r & 7)) << 4);
            cp16(base_ + off, kb0 + (size_t)r * QKV_ST + c * 8);
            cp16(base_ + 8192 + off, vb0 + (size_t)r * QKV_ST + c * 8);
        }
        CP_COMMIT();
    }
    if (ktmax > 1) F_ISSUE(1, 1);

    float o[8][4];
#pragma unroll
    for (int nt = 0; nt < 8; nt++)
#pragma unroll
        for (int j = 0; j < 4; j++) o[nt][j] = 0.f;
    float lacc[4] = {0.f, 0.f, 0.f, 0.f};   // denominator via ones-MMA
    const uint32_t onesb[2] = {0x3F803F80u, 0x3F803F80u};   // bf16 1.0 x4
    uint32_t aq[4][4];

    int br = 0;
    for (int kt = 0; kt < ktmax; kt++) {
        if (kt + 1 < ktmax) CP_WAIT1(); else CP_WAIT0();
        __syncthreads();
        if (kt + 2 < ktmax) {
            int bi = br + 2; if (bi >= 3) bi -= 3;
            F_ISSUE(kt + 2, bi);
        }
        if (kt == 0) {
#pragma unroll
            for (int ks = 0; ks < 4; ks++) {
                int row = wid * 16 + (lane & 7) + ((lane & 8) ? 8 : 0);
                int c = ks * 2 + ((lane >> 4) & 1);
                ldsm4(aq[ks], sb + row * 128 + ((c ^ (row & 7)) << 4));
            }
        }
        if (kt * 64 <= rowbase + 15) {
            uint32_t base = sb + FQ_SZ + (uint32_t)br * FKV_SZ;
            float S[8][4];
#pragma unroll
            for (int nt = 0; nt < 8; nt++)
#pragma unroll
                for (int j = 0; j < 4; j++) S[nt][j] = 0.f;

            // S = Q K^T (log2-domain scale folded into Q)
#pragma unroll
            for (int ks = 0; ks < 4; ks++) {
#pragma unroll
                for (int j = 0; j < 4; j++) {
                    uint32_t kbf[4];
                    int krow = j * 16 + (lane & 7) + ((lane & 16) ? 8 : 0);
                    int c = ks * 2 + ((lane >> 3) & 1);
                    ldsm4(kbf, base + krow * 128 + ((c ^ (krow & 7)) << 4));
                    mma16(S[2 * j], aq[ks], &kbf[0]);
                    mma16(S[2 * j + 1], aq[ks], &kbf[2]);
                }
            }

            // causal mask (diagonal tiles only): ex2(bf16(-1e30)) == 0
            if (kt * 64 + 63 > rowbase) {
#pragma unroll
                for (int nt = 0; nt < 8; nt++)
#pragma unroll
                    for (int j = 0; j < 4; j++) {
                        int col = kt * 64 + nt * 8 + 2 * tg + (j & 1);
                        int row = rowbase + g + ((j >> 1) << 3);
                        if (col > row) S[nt][j] = -1e30f;
                    }
            }

            // P = exp2(S) computed in bf16x2 (2 exps per MUFU op); the result
            // IS the PV A-fragment. l accumulated by ones-MMA below.
#pragma unroll
            for (int ksp = 0; ksp < 4; ksp++) {
                uint32_t ap[4] = {
                    ex2b(pk(S[2 * ksp][0], S[2 * ksp][1])),
                    ex2b(pk(S[2 * ksp][2], S[2 * ksp][3])),
                    ex2b(pk(S[2 * ksp + 1][0], S[2 * ksp + 1][1])),
                    ex2b(pk(S[2 * ksp + 1][2], S[2 * ksp + 1][3]))};
                mma16(lacc, ap, onesb);   // l += P @ 1
#pragma unroll
                for (int j = 0; j < 4; j++) {
                    uint32_t vbf[4];
                    int krow = ksp * 16 + (lane & 7) + ((lane & 8) ? 8 : 0);
                    int c = j * 2 + ((lane >> 4) & 1);
                    ldsm4t(vbf, base + 8192 + krow * 128 + ((c ^ (krow & 7)) << 4));
                    mma16(o[2 * j], ap, &vbf[0]);
                    mma16(o[2 * j + 1], ap, &vbf[2]);
                }
            }
        }
        if (++br == 3) br = 0;
    }

    // every lane already holds the full row sums (ones-MMA) — no shuffles
    float inv0 = 1.f / lacc[0], inv1 = 1.f / lacc[2];
    uint32_t* c0p = (uint32_t*)(ctx + (size_t)(b * SEQT + rowbase + g) * 512 + h * 64);
    uint32_t* c1p = (uint32_t*)(ctx + (size_t)(b * SEQT + rowbase + g + 8) * 512 + h * 64);
#pragma unroll
    for (int nt = 0; nt < 8; nt++) {
        int cw = (nt * 8 + 2 * tg) >> 1;
        c0p[cw] = pk(o[nt][0] * inv0, o[nt][1] * inv0);
        c1p[cw] = pk(o[nt][2] * inv1, o[nt][3] * inv1);
    }
#undef F_ISSUE
}

// ===========================================================================
extern "C" void kernel_launch(void* const* d_in, const int* in_sizes, int n_in,
                              void* d_out, int out_size) {
    const float* x     = (const float*)d_in[0];
    const float* gamma = (const float*)d_in[1];
    const float* beta  = (const float*)d_in[2];
    const float* wq = (const float*)d_in[3];
    const float* bq = (const float*)d_in[4];
    const float* wk = (const float*)d_in[5];
    const float* bk = (const float*)d_in[6];
    const float* wv = (const float*)d_in[7];
    const float* bv = (const float*)d_in[8];
    const float* wo = (const float*)d_in[9];
    const float* bo = (const float*)d_in[10];
    float* out = (float*)d_out;

    __nv_bfloat16 *hn, *qkv, *cb, *wqkv, *wob;
    float *bqkv;
    cudaGetSymbolAddress((void**)&hn,   g_hn);
    cudaGetSymbolAddress((void**)&qkv,  g_qkv);
    cudaGetSymbolAddress((void**)&cb,   g_ctx);
    cudaGetSymbolAddress((void**)&wqkv, g_wqkv);
    cudaGetSymbolAddress((void**)&wob,  g_wo);
    cudaGetSymbolAddress((void**)&bqkv, g_bqkv);

    ln_kernel<<<dim3(SEQT / 32, BATCH), 512>>>(x, gamma, beta, hn);
    cvt_pack<<<1024, 256>>>(wq, wk, wv, wo, bq, bk, bv, wqkv, wob, bqkv);

    cudaFuncSetAttribute(gemm_qkv, cudaFuncAttributeMaxDynamicSharedMemorySize, GEMM_SMEM);
    cudaFuncSetAttribute(gemm_out, cudaFuncAttributeMaxDynamicSharedMemorySize, GEMM_SMEM);
    gemm_qkv<<<dim3(12, MROWS / 128), 256, GEMM_SMEM>>>(hn, wqkv, bqkv, qkv);

    cudaFuncSetAttribute(flash_bf16, cudaFuncAttributeMaxDynamicSharedMemorySize, FLASH_SMEM);
    flash_bf16<<<dim3(SEQT / 128, BATCH * NH), 256, FLASH_SMEM>>>(qkv, cb);

    gemm_out<<<dim3(4, MROWS / 128), 256, GEMM_SMEM>>>(cb, wob, bo, x, out);
}

// round 15
// speedup vs baseline: 1.0531x; 1.0531x over previous
#include <cuda_runtime.h>
#include <cuda_bf16.h>
#include <cstdint>
#include <math.h>

#define BATCH 8
#define CIN 512
#define SEQT 2048
#define DF 512
#define NH 8
#define DH 64
#define MROWS (BATCH*SEQT)   // 16384

// Scratch (allocation-free rule: __device__ globals)
__device__ __nv_bfloat16 g_hn  [MROWS * DF];          // LN output
__device__ __nv_bfloat16 g_qkv [MROWS * 3 * DF];      // fused q|k|v, row stride 1536
__device__ __nv_bfloat16 g_ctx [MROWS * DF];
__device__ __nv_bfloat16 g_wqkv[CIN * 3 * DF];        // packed bf16 weights [512][1536]
__device__ __nv_bfloat16 g_wo  [CIN * DF];
__device__ float         g_bqkv[3 * DF];

// ===========================================================================
// helpers
// ===========================================================================
__device__ __forceinline__ uint32_t pk(float lo, float hi) {
    uint32_t d;
    asm("cvt.rn.bf16x2.f32 %0, %1, %2;" : "=r"(d) : "f"(hi), "f"(lo));
    return d;
}
__device__ __forceinline__ uint32_t ex2b(uint32_t x) {   // two exp2 per MUFU op
    uint32_t y;
    asm("ex2.approx.ftz.bf16x2 %0, %1;" : "=r"(y) : "r"(x));
    return y;
}
__device__ __forceinline__ void mma16(float* d, const uint32_t* a, const uint32_t* b) {
    asm volatile(
        "mma.sync.aligned.m16n8k16.row.col.f32.bf16.bf16.f32 "
        "{%0,%1,%2,%3}, {%4,%5,%6,%7}, {%8,%9}, {%0,%1,%2,%3};"
        : "+f"(d[0]), "+f"(d[1]), "+f"(d[2]), "+f"(d[3])
        : "r"(a[0]), "r"(a[1]), "r"(a[2]), "r"(a[3]), "r"(b[0]), "r"(b[1]));
}
__device__ __forceinline__ void ldsm4(uint32_t* r, uint32_t a) {
    asm volatile("ldmatrix.sync.aligned.m8n8.x4.shared.b16 {%0,%1,%2,%3}, [%4];"
        : "=r"(r[0]), "=r"(r[1]), "=r"(r[2]), "=r"(r[3]) : "r"(a));
}
__device__ __forceinline__ void ldsm4t(uint32_t* r, uint32_t a) {
    asm volatile("ldmatrix.sync.aligned.m8n8.x4.trans.shared.b16 {%0,%1,%2,%3}, [%4];"
        : "=r"(r[0]), "=r"(r[1]), "=r"(r[2]), "=r"(r[3]) : "r"(a));
}
__device__ __forceinline__ void cp16(uint32_t saddr, const void* g) {
    asm volatile("cp.async.cg.shared.global [%0], [%1], 16;" :: "r"(saddr), "l"(g));
}
#define CP_COMMIT() asm volatile("cp.async.commit_group;" ::: "memory")
#define CP_WAIT1()  asm volatile("cp.async.wait_group 1;" ::: "memory")
#define CP_WAIT0()  asm volatile("cp.async.wait_group 0;" ::: "memory")
__device__ __forceinline__ uint32_t smem_u32(const void* p) {
    uint32_t a;
    asm("{ .reg .u64 t; cvta.to.shared.u64 t, %1; cvt.u32.u64 %0, t; }" : "=r"(a) : "l"(p));
    return a;
}

// ===========================================================================
// LayerNorm: x (B, C, T) -> hn (B*T, C) bf16, coalesced two-pass tiles
// (round-13 configuration — single-pass regressed twice)
// ===========================================================================
__global__ void ln_kernel(const float* __restrict__ x, const float* __restrict__ gamma,
                          const float* __restrict__ beta, __nv_bfloat16* __restrict__ hn) {
    int b = blockIdx.y, t0 = blockIdx.x * 32;
    int tid = threadIdx.x;
    int tx = tid & 31, cy = tid >> 5;   // 8 c-lanes
    const float* xp = x + (size_t)b * CIN * SEQT + t0;
    float s = 0.f, s2 = 0.f;
#pragma unroll 8
    for (int c = cy; c < CIN; c += 8) {
        float v = xp[(size_t)c * SEQT + tx];
        s += v; s2 += v * v;
    }
    __shared__ float ss[8][32], ss2[8][32], mean_s[32], rstd_s[32];
    ss[cy][tx] = s; ss2[cy][tx] = s2;
    __syncthreads();
    if (cy == 0) {
        float S = 0.f, S2 = 0.f;
#pragma unroll
        for (int i = 0; i < 8; i++) { S += ss[i][tx]; S2 += ss2[i][tx]; }
        float mean = S * (1.f / CIN);
        float var = S2 * (1.f / CIN) - mean * mean;
        mean_s[tx] = mean;
        rstd_s[tx] = rsqrtf(var + 1e-5f);
    }
    __syncthreads();
    float mean = mean_s[tx], rstd = rstd_s[tx];
    __shared__ float tile[32][33];
    for (int c0 = 0; c0 < CIN; c0 += 32) {
#pragma unroll
        for (int j = 0; j < 4; j++) {
            int c = c0 + cy + j * 8;
            tile[cy + j * 8][tx] = (xp[(size_t)c * SEQT + tx] - mean) * rstd * gamma[c] + beta[c];
        }
        __syncthreads();
#pragma unroll
        for (int j = 0; j < 4; j++) {
            int t = cy + j * 8;
            hn[(size_t)(b * SEQT + t0 + t) * CIN + c0 + tx] = __float2bfloat16(tile[tx][t]);
        }
        __syncthreads();
    }
}

// ===========================================================================
// single pack/convert: wq|wk|wv -> wqkv[512][1536] bf16, wo -> bf16,
// bq|bk|bv -> bqkv[1536] fp32
// ===========================================================================
__global__ void cvt_pack(const float* __restrict__ wq, const float* __restrict__ wk,
                         const float* __restrict__ wv, const float* __restrict__ wo,
                         const float* __restrict__ bq, const float* __restrict__ bk,
                         const float* __restrict__ bv,
                         __nv_bfloat16* __restrict__ wqkv, __nv_bfloat16* __restrict__ wob,
                         float* __restrict__ bqkv) {
    int t = blockIdx.x * 256 + threadIdx.x;
    int i = t * 4;                       // over 4*512*512 = 1M floats
    int w = i >> 18;                     // which weight
    int r = i & 0x3FFFF;
    const float* src = (w == 0) ? wq : (w == 1) ? wk : (w == 2) ? wv : wo;
    float4 v = *(const float4*)(src + r);
    uint2 p = {pk(v.x, v.y), pk(v.z, v.w)};
    if (w < 3) {
        int kk = r >> 9, n = r & 511;
        *(uint2*)(wqkv + (size_t)kk * 1536 + w * 512 + n) = p;
    } else {
        *(uint2*)(wob + r) = p;
    }
    if (t < 3 * DF)
        bqkv[t] = (t < 512) ? bq[t] : (t < 1024) ? bk[t - 512] : bv[t - 1024];
}

// ===========================================================================
// fused QKV GEMM: qkv[M,1536] = hn[M,512] @ wqkv[512,1536] + bqkv
// 128x128 tile, BK=64, 256 thr. 3-stage cp.async, ONE barrier per k-tile.
// Epilogue staged through smem for fully coalesced 16B global stores.
// ===========================================================================
#define GA_SZ 16384
#define GB_SZ 16384
#define GBUF  (GA_SZ + GB_SZ)
#define GEMM_SMEM (3 * GBUF)   // 98304
#define CST 68                  // staging row stride in 32-bit words (conflict-free)

__global__ __launch_bounds__(256, 2)
void gemm_qkv(const __nv_bfloat16* __restrict__ A, const __nv_bfloat16* __restrict__ W,
              const float* __restrict__ bias, __nv_bfloat16* __restrict__ C) {
    extern __shared__ char sm[];
    uint32_t sb = smem_u32(sm);
    const int tid = threadIdx.x;
    const int wid = tid >> 5, lane = tid & 31;
    const int g = lane >> 2, tg = lane & 3;
    const int bm = blockIdx.y * 128, bn = blockIdx.x * 128;
    const int wm = (wid & 3) * 32, wn = (wid >> 2) * 64;
    const float scale = (bn < 512) ? 0.125f * 1.44269504088896f : 1.0f;

#define G_ISSUE(kt, buf) do {                                                        \
        uint32_t base_ = sb + (uint32_t)(buf) * GBUF;                                \
        _Pragma("unroll")                                                            \
        for (int i_ = 0; i_ < 4; i_++) {                                             \
            int idx = tid + i_ * 256;                                                \
            int r = idx >> 3, c = idx & 7;                                           \
            cp16(base_ + r * 128 + ((c ^ (r & 7)) << 4),                             \
                 A + (size_t)(bm + r) * 512 + (kt) * 64 + c * 8);                    \
        }                                                                            \
        _Pragma("unroll")                                                            \
        for (int i_ = 0; i_ < 4; i_++) {                                             \
            int idx = tid + i_ * 256;                                                \
            int r = idx >> 4, c = idx & 15;                                          \
            cp16(base_ + GA_SZ + r * 256 + ((c ^ (r & 7)) << 4),                     \
                 W + (size_t)((kt) * 64 + r) * 1536 + bn + c * 8);                   \
        }                                                                            \
        CP_COMMIT();                                                                 \
    } while (0)

    float acc[2][8][4];
#pragma unroll
    for (int mt = 0; mt < 2; mt++)
#pragma unroll
        for (int nt = 0; nt < 8; nt++)
#pragma unroll
            for (int j = 0; j < 4; j++) acc[mt][nt][j] = 0.f;

    G_ISSUE(0, 0);
    G_ISSUE(1, 1);
    int br = 0;
    for (int kt = 0; kt < 8; kt++) {
        if (kt < 7) CP_WAIT1(); else CP_WAIT0();
        __syncthreads();
        if (kt + 2 < 8) {
            int bi = br + 2; if (bi >= 3) bi -= 3;
            G_ISSUE(kt + 2, bi);
        }
        uint32_t base = sb + br * GBUF;
#pragma unroll
        for (int ks = 0; ks < 4; ks++) {
            uint32_t a[2][4];
#pragma unroll
            for (int mt = 0; mt < 2; mt++) {
                int row = wm + mt * 16 + (lane & 7) + ((lane & 8) ? 8 : 0);
                int c = ks * 2 + ((lane >> 4) & 1);
                ldsm4(a[mt], base + row * 128 + ((c ^ (row & 7)) << 4));
            }
            uint32_t bb[4][4];
#pragma unroll
            for (int j = 0; j < 4; j++) {
                int krow = ks * 16 + (lane & 7) + ((lane & 8) ? 8 : 0);
                int c = ((wn + j * 16) >> 3) + ((lane >> 4) & 1);
                ldsm4t(bb[j], base + GA_SZ + krow * 256 + ((c ^ (krow & 7)) << 4));
            }
#pragma unroll
            for (int mt = 0; mt < 2; mt++)
#pragma unroll
                for (int j = 0; j < 4; j++) {
                    mma16(acc[mt][2 * j], a[mt], &bb[j][0]);
                    mma16(acc[mt][2 * j + 1], a[mt], &bb[j][2]);
                }
        }
        if (++br == 3) br = 0;
    }

    // epilogue: stage bf16 C tile in smem (stride CST words), then coalesced
    // STG.128 stores (warp = 2 rows x 256B contiguous).
    __syncthreads();
    uint32_t* cs = (uint32_t*)sm;
#pragma unroll
    for (int mt = 0; mt < 2; mt++) {
        int r0 = wm + mt * 16 + g;
#pragma unroll
        for (int nt = 0; nt < 8; nt++) {
            int col = wn + nt * 8 + 2 * tg;
            float b0 = bias[bn + col], b1 = bias[bn + col + 1];
            cs[r0 * CST + (col >> 1)] =
                pk((acc[mt][nt][0] + b0) * scale, (acc[mt][nt][1] + b1) * scale);
            cs[(r0 + 8) * CST + (col >> 1)] =
                pk((acc[mt][nt][2] + b0) * scale, (acc[mt][nt][3] + b1) * scale);
        }
    }
    __syncthreads();
    uint32_t* Cw = (uint32_t*)C;
#pragma unroll
    for (int i = 0; i < 8; i++) {
        int f = tid + i * 256;          // 2048 16B-chunks: 128 rows x 16
        int r = f >> 4, c4 = (f & 15) << 2;
        uint4 v = *(uint4*)(cs + r * CST + c4);
        *(uint4*)(Cw + (size_t)(bm + r) * 768 + (bn >> 1) + c4) = v;
    }
#undef G_ISSUE
}

// ===========================================================================
// output GEMM + residual + transpose: out[b][c][t] = x[b][c][t] +
//   (ctx[b*T+t][:] @ wo)[c] + bo[c].  3-stage, one barrier per k-tile.
// Epilogue staged through smem transposed [c][t] so the residual add and
// store run as fully coalesced LDG.128/STG.128 along t.
// ===========================================================================
#define OST 132   // fp32 staging stride (words): conflict-free, 16B-aligned rows

__global__ __launch_bounds__(256, 2)
void gemm_out(const __nv_bfloat16* __restrict__ A, const __nv_bfloat16* __restrict__ W,
              const float* __restrict__ bias, const float* __restrict__ x,
              float* __restrict__ out) {
    extern __shared__ char sm[];
    uint32_t sb = smem_u32(sm);
    const int tid = threadIdx.x;
    const int wid = tid >> 5, lane = tid & 31;
    const int g = lane >> 2, tg = lane & 3;
    const int bm = blockIdx.y * 128, bn = blockIdx.x * 128;
    const int wm = (wid & 3) * 32, wn = (wid >> 2) * 64;

#define G_ISSUE(kt, buf) do {                                                        \
        uint32_t base_ = sb + (uint32_t)(buf) * GBUF;                                \
        _Pragma("unroll")                                                            \
        for (int i_ = 0; i_ < 4; i_++) {                                             \
            int idx = tid + i_ * 256;                                                \
            int r = idx >> 3, c = idx & 7;                                           \
            cp16(base_ + r * 128 + ((c ^ (r & 7)) << 4),                             \
                 A + (size_t)(bm + r) * 512 + (kt) * 64 + c * 8);                    \
        }                                                                            \
        _Pragma("unroll")                                                            \
        for (int i_ = 0; i_ < 4; i_++) {                                             \
            int idx = tid + i_ * 256;                                                \
            int r = idx >> 4, c = idx & 15;                                          \
            cp16(base_ + GA_SZ + r * 256 + ((c ^ (r & 7)) << 4),                     \
                 W + (size_t)((kt) * 64 + r) * 512 + bn + c * 8);                    \
        }                                                                            \
        CP_COMMIT();                                                                 \
    } while (0)

    float acc[2][8][4];
#pragma unroll
    for (int mt = 0; mt < 2; mt++)
#pragma unroll
        for (int nt = 0; nt < 8; nt++)
#pragma unroll
            for (int j = 0; j < 4; j++) acc[mt][nt][j] = 0.f;

    G_ISSUE(0, 0);
    G_ISSUE(1, 1);
    int br = 0;
    for (int kt = 0; kt < 8; kt++) {
        if (kt < 7) CP_WAIT1(); else CP_WAIT0();
        __syncthreads();
        if (kt + 2 < 8) {
            int bi = br + 2; if (bi >= 3) bi -= 3;
            G_ISSUE(kt + 2, bi);
        }
        uint32_t base = sb + br * GBUF;
#pragma unroll
        for (int ks = 0; ks < 4; ks++) {
            uint32_t a[2][4];
#pragma unroll
            for (int mt = 0; mt < 2; mt++) {
                int row = wm + mt * 16 + (lane & 7) + ((lane & 8) ? 8 : 0);
                int c = ks * 2 + ((lane >> 4) & 1);
                ldsm4(a[mt], base + row * 128 + ((c ^ (row & 7)) << 4));
            }
            uint32_t bb[4][4];
#pragma unroll
            for (int j = 0; j < 4; j++) {
                int krow = ks * 16 + (lane & 7) + ((lane & 8) ? 8 : 0);
                int c = ((wn + j * 16) >> 3) + ((lane >> 4) & 1);
                ldsm4t(bb[j], base + GA_SZ + krow * 256 + ((c ^ (krow & 7)) << 4));
            }
#pragma unroll
            for (int mt = 0; mt < 2; mt++)
#pragma unroll
                for (int j = 0; j < 4; j++) {
                    mma16(acc[mt][2 * j], a[mt], &bb[j][0]);
                    mma16(acc[mt][2 * j + 1], a[mt], &bb[j][2]);
                }
        }
        if (++br == 3) br = 0;
    }

    // epilogue phase 1: stage (acc + bias) transposed [c_local][t_local]
    __syncthreads();
    float* cs = (float*)sm;
#pragma unroll
    for (int mt = 0; mt < 2; mt++) {
        int t_l = wm + mt * 16 + g;
#pragma unroll
        for (int nt = 0; nt < 8; nt++) {
            int c_l = wn + nt * 8 + 2 * tg;
            float b0 = bias[bn + c_l], b1 = bias[bn + c_l + 1];
            cs[c_l * OST + t_l]           = acc[mt][nt][0] + b0;
            cs[(c_l + 1) * OST + t_l]     = acc[mt][nt][1] + b1;
            cs[c_l * OST + t_l + 8]       = acc[mt][nt][2] + b0;
            cs[(c_l + 1) * OST + t_l + 8] = acc[mt][nt][3] + b1;
        }
    }
    __syncthreads();
    // epilogue phase 2: residual add + store, coalesced along t
    // rows bm..bm+127 are one batch (2048 % 128 == 0): b = bm>>11, t0 = bm&2047
    const int bI = bm >> 11, t0g = bm & 2047;
#pragma unroll
    for (int i = 0; i < 16; i++) {
        int f = tid + i * 256;                // 4096 chunks: 128 c x 32 chunks
        int c_l = f >> 5, ch = (f & 31) << 2;
        size_t gidx = ((size_t)(bI * 512 + bn + c_l)) * 2048 + t0g + ch;
        float4 xv = *(const float4*)(x + gidx);
        float4 v  = *(float4*)(cs + c_l * OST + ch);
        v.x += xv.x; v.y += xv.y; v.z += xv.z; v.w += xv.w;
        *(float4*)(out + gidx) = v;
    }
#undef G_ISSUE
}

// ===========================================================================
// Flash attention, causal, bf16 mma, qkv packed (row stride 1536).
// NO-MAX softmax, exp2 via bf16x2 MUFU (2 exps/op), denominator via
// ones-MMA (l = P @ 1) on the tensor pipe — measured-best configuration.
// 3-stage KV pipeline, one barrier per tile.
// ===========================================================================
#define FQ_SZ 16384
#define FKV_SZ 16384
#define FLASH_SMEM (FQ_SZ + 3 * FKV_SZ)   // 65536
#define QKV_ST 1536

__global__ __launch_bounds__(256, 2)
void flash_bf16(const __nv_bfloat16* __restrict__ qkv, __nv_bfloat16* __restrict__ ctx) {
    extern __shared__ char sm[];
    uint32_t sb = smem_u32(sm);
    const int qt = (int)(gridDim.x - 1 - blockIdx.x);   // heavy tiles first
    const int bh = blockIdx.y;
    const int b = bh >> 3, h = bh & 7;
    const int qb = qt * 128;
    const int tid = threadIdx.x, wid = tid >> 5, lane = tid & 31;
    const int g = lane >> 2, tg = lane & 3;
    const int rowbase = qb + wid * 16;
    const int ktmax = 2 * qt + 2;

    const __nv_bfloat16* qp  = qkv + (size_t)(b * SEQT + qb) * QKV_ST + h * 64;
    const __nv_bfloat16* kb0 = qkv + (size_t)b * SEQT * QKV_ST + 512 + h * 64;
    const __nv_bfloat16* vb0 = qkv + (size_t)b * SEQT * QKV_ST + 1024 + h * 64;

#define F_ISSUE(kt, buf) do {                                                        \
        uint32_t base_ = sb + FQ_SZ + (uint32_t)(buf) * FKV_SZ;                      \
        const __nv_bfloat16* kp_ = kb0 + (size_t)(kt) * 64 * QKV_ST;                 \
        const __nv_bfloat16* vp_ = vb0 + (size_t)(kt) * 64 * QKV_ST;                 \
        _Pragma("unroll")                                                            \
        for (int i_ = 0; i_ < 2; i_++) {                                             \
            int idx = tid + i_ * 256;                                                \
            int r = idx >> 3, c = idx & 7;                                           \
            uint32_t off = r * 128 + ((c ^ (r & 7)) << 4);                           \
            cp16(base_ + off, kp_ + (size_t)r * QKV_ST + c * 8);                     \
            cp16(base_ + 8192 + off, vp_ + (size_t)r * QKV_ST + c * 8);              \
        }                                                                            \
        CP_COMMIT();                                                                 \
    } while (0)

    // group 0: Q + KV(0); group 1: KV(1)
#pragma unroll
    for (int i = 0; i < 4; i++) {
        int idx = tid + i * 256;
        int r = idx >> 3, c = idx & 7;
        cp16(sb + r * 128 + ((c ^ (r & 7)) << 4), qp + (size_t)r * QKV_ST + c * 8);
    }
    {
        uint32_t base_ = sb + FQ_SZ;
#pragma unroll
        for (int i = 0; i < 2; i++) {
            int idx = tid + i * 256;
            int r = idx >> 3, c = idx & 7;
            uint32_t off = r * 128 + ((c ^ (r & 7)) << 4);
            cp16(base_ + off, kb0 + (size_t)r * QKV_ST + c * 8);
            cp16(base_ + 8192 + off, vb0 + (size_t)r * QKV_ST + c * 8);
        }
        CP_COMMIT();
    }
    if (ktmax > 1) F_ISSUE(1, 1);

    float o[8][4];
#pragma unroll
    for (int nt = 0; nt < 8; nt++)
#pragma unroll
        for (int j = 0; j < 4; j++) o[nt][j] = 0.f;
    float lacc[4] = {0.f, 0.f, 0.f, 0.f};   // denominator via ones-MMA
    const uint32_t onesb[2] = {0x3F803F80u, 0x3F803F80u};   // bf16 1.0 x4
    uint32_t aq[4][4];

    int br = 0;
    for (int kt = 0; kt < ktmax; kt++) {
        if (kt + 1 < ktmax) CP_WAIT1(); else CP_WAIT0();
        __syncthreads();
        if (kt + 2 < ktmax) {
            int bi = br + 2; if (bi >= 3) bi -= 3;
            F_ISSUE(kt + 2, bi);
        }
        if (kt == 0) {
#pragma unroll
            for (int ks = 0; ks < 4; ks++) {
                int row = wid * 16 + (lane & 7) + ((lane & 8) ? 8 : 0);
                int c = ks * 2 + ((lane >> 4) & 1);
                ldsm4(aq[ks], sb + row * 128 + ((c ^ (row & 7)) << 4));
            }
        }
        if (kt * 64 <= rowbase + 15) {
            uint32_t base = sb + FQ_SZ + (uint32_t)br * FKV_SZ;
            float S[8][4];
#pragma unroll
            for (int nt = 0; nt < 8; nt++)
#pragma unroll
                for (int j = 0; j < 4; j++) S[nt][j] = 0.f;

            // S = Q K^T (log2-domain scale folded into Q)
#pragma unroll
            for (int ks = 0; ks < 4; ks++) {
#pragma unroll
                for (int j = 0; j < 4; j++) {
                    uint32_t kbf[4];
                    int krow = j * 16 + (lane & 7) + ((lane & 16) ? 8 : 0);
                    int c = ks * 2 + ((lane >> 3) & 1);
                    ldsm4(kbf, base + krow * 128 + ((c ^ (krow & 7)) << 4));
                    mma16(S[2 * j], aq[ks], &kbf[0]);
                    mma16(S[2 * j + 1], aq[ks], &kbf[2]);
                }
            }

            // causal mask (diagonal tiles only): ex2(bf16(-1e30)) == 0
            if (kt * 64 + 63 > rowbase) {
#pragma unroll
                for (int nt = 0; nt < 8; nt++)
#pragma unroll
                    for (int j = 0; j < 4; j++) {
                        int col = kt * 64 + nt * 8 + 2 * tg + (j & 1);
                        int row = rowbase + g + ((j >> 1) << 3);
                        if (col > row) S[nt][j] = -1e30f;
                    }
            }

            // P = exp2(S) computed in bf16x2 (2 exps per MUFU op); the result
            // IS the PV A-fragment. l accumulated by ones-MMA below.
#pragma unroll
            for (int ksp = 0; ksp < 4; ksp++) {
                uint32_t ap[4] = {
                    ex2b(pk(S[2 * ksp][0], S[2 * ksp][1])),
                    ex2b(pk(S[2 * ksp][2], S[2 * ksp][3])),
                    ex2b(pk(S[2 * ksp + 1][0], S[2 * ksp + 1][1])),
                    ex2b(pk(S[2 * ksp + 1][2], S[2 * ksp + 1][3]))};
                mma16(lacc, ap, onesb);   // l += P @ 1
#pragma unroll
                for (int j = 0; j < 4; j++) {
                    uint32_t vbf[4];
                    int krow = ksp * 16 + (lane & 7) + ((lane & 8) ? 8 : 0);
                    int c = j * 2 + ((lane >> 4) & 1);
                    ldsm4t(vbf, base + 8192 + krow * 128 + ((c ^ (krow & 7)) << 4));
                    mma16(o[2 * j], ap, &vbf[0]);
                    mma16(o[2 * j + 1], ap, &vbf[2]);
                }
            }
        }
        if (++br == 3) br = 0;
    }

    // every lane already holds the full row sums (ones-MMA) — no shuffles
    float inv0 = 1.f / lacc[0], inv1 = 1.f / lacc[2];
    uint32_t* c0p = (uint32_t*)(ctx + (size_t)(b * SEQT + rowbase + g) * 512 + h * 64);
    uint32_t* c1p = (uint32_t*)(ctx + (size_t)(b * SEQT + rowbase + g + 8) * 512 + h * 64);
#pragma unroll
    for (int nt = 0; nt < 8; nt++) {
        int cw = (nt * 8 + 2 * tg) >> 1;
        c0p[cw] = pk(o[nt][0] * inv0, o[nt][1] * inv0);
        c1p[cw] = pk(o[nt][2] * inv1, o[nt][3] * inv1);
    }
#undef F_ISSUE
}

// ===========================================================================
extern "C" void kernel_launch(void* const* d_in, const int* in_sizes, int n_in,
                              void* d_out, int out_size) {
    const float* x     = (const float*)d_in[0];
    const float* gamma = (const float*)d_in[1];
    const float* beta  = (const float*)d_in[2];
    const float* wq = (const float*)d_in[3];
    const float* bq = (const float*)d_in[4];
    const float* wk = (const float*)d_in[5];
    const float* bk = (const float*)d_in[6];
    const float* wv = (const float*)d_in[7];
    const float* bv = (const float*)d_in[8];
    const float* wo = (const float*)d_in[9];
    const float* bo = (const float*)d_in[10];
    float* out = (float*)d_out;

    __nv_bfloat16 *hn, *qkv, *cb, *wqkv, *wob;
    float *bqkv;
    cudaGetSymbolAddress((void**)&hn,   g_hn);
    cudaGetSymbolAddress((void**)&qkv,  g_qkv);
    cudaGetSymbolAddress((void**)&cb,   g_ctx);
    cudaGetSymbolAddress((void**)&wqkv, g_wqkv);
    cudaGetSymbolAddress((void**)&wob,  g_wo);
    cudaGetSymbolAddress((void**)&bqkv, g_bqkv);

    ln_kernel<<<dim3(SEQT / 32, BATCH), 256>>>(x, gamma, beta, hn);
    cvt_pack<<<1024, 256>>>(wq, wk, wv, wo, bq, bk, bv, wqkv, wob, bqkv);

    cudaFuncSetAttribute(gemm_qkv, cudaFuncAttributeMaxDynamicSharedMemorySize, GEMM_SMEM);
    cudaFuncSetAttribute(gemm_out, cudaFuncAttributeMaxDynamicSharedMemorySize, GEMM_SMEM);
    gemm_qkv<<<dim3(12, MROWS / 128), 256, GEMM_SMEM>>>(hn, wqkv, bqkv, qkv);

    cudaFuncSetAttribute(flash_bf16, cudaFuncAttributeMaxDynamicSharedMemorySize, FLASH_SMEM);
    flash_bf16<<<dim3(SEQT / 128, BATCH * NH), 256, FLASH_SMEM>>>(qkv, cb);

    gemm_out<<<dim3(4, MROWS / 128), 256, GEMM_SMEM>>>(cb, wob, bo, x, out);
}

// round 16
// speedup vs baseline: 1.1565x; 1.0982x over previous
#include <cuda_runtime.h>
#include <cuda_bf16.h>
#include <cstdint>
#include <math.h>

#define BATCH 8
#define CIN 512
#define SEQT 2048
#define DF 512
#define NH 8
#define DH 64
#define MROWS (BATCH*SEQT)   // 16384

// Scratch (allocation-free rule: __device__ globals)
__device__ __nv_bfloat16 g_hn  [MROWS * DF];          // LN output
__device__ __nv_bfloat16 g_qkv [MROWS * 3 * DF];      // fused q|k|v, row stride 1536
__device__ __nv_bfloat16 g_ctx [MROWS * DF];
__device__ __nv_bfloat16 g_wqkv[CIN * 3 * DF];        // packed bf16 weights [512][1536]
__device__ __nv_bfloat16 g_wo  [CIN * DF];
__device__ float         g_bqkv[3 * DF];

// ===========================================================================
// helpers
// ===========================================================================
__device__ __forceinline__ uint32_t pk(float lo, float hi) {
    uint32_t d;
    asm("cvt.rn.bf16x2.f32 %0, %1, %2;" : "=r"(d) : "f"(hi), "f"(lo));
    return d;
}
__device__ __forceinline__ uint32_t ex2b(uint32_t x) {   // two exp2 per MUFU op
    uint32_t y;
    asm("ex2.approx.ftz.bf16x2 %0, %1;" : "=r"(y) : "r"(x));
    return y;
}
__device__ __forceinline__ void mma16(float* d, const uint32_t* a, const uint32_t* b) {
    asm volatile(
        "mma.sync.aligned.m16n8k16.row.col.f32.bf16.bf16.f32 "
        "{%0,%1,%2,%3}, {%4,%5,%6,%7}, {%8,%9}, {%0,%1,%2,%3};"
        : "+f"(d[0]), "+f"(d[1]), "+f"(d[2]), "+f"(d[3])
        : "r"(a[0]), "r"(a[1]), "r"(a[2]), "r"(a[3]), "r"(b[0]), "r"(b[1]));
}
__device__ __forceinline__ void ldsm4(uint32_t* r, uint32_t a) {
    asm volatile("ldmatrix.sync.aligned.m8n8.x4.shared.b16 {%0,%1,%2,%3}, [%4];"
        : "=r"(r[0]), "=r"(r[1]), "=r"(r[2]), "=r"(r[3]) : "r"(a));
}
__device__ __forceinline__ void ldsm4t(uint32_t* r, uint32_t a) {
    asm volatile("ldmatrix.sync.aligned.m8n8.x4.trans.shared.b16 {%0,%1,%2,%3}, [%4];"
        : "=r"(r[0]), "=r"(r[1]), "=r"(r[2]), "=r"(r[3]) : "r"(a));
}
__device__ __forceinline__ void cp16(uint32_t saddr, const void* g) {
    asm volatile("cp.async.cg.shared.global [%0], [%1], 16;" :: "r"(saddr), "l"(g));
}
#define CP_COMMIT() asm volatile("cp.async.commit_group;" ::: "memory")
#define CP_WAIT1()  asm volatile("cp.async.wait_group 1;" ::: "memory")
#define CP_WAIT0()  asm volatile("cp.async.wait_group 0;" ::: "memory")
__device__ __forceinline__ uint32_t smem_u32(const void* p) {
    uint32_t a;
    asm("{ .reg .u64 t; cvta.to.shared.u64 t, %1; cvt.u32.u64 %0, t; }" : "=r"(a) : "l"(p));
    return a;
}

// ===========================================================================
// Fused LN + weight convert (one launch, independent block ranges):
//   blocks [0, 512): LayerNorm x (B,C,T) -> hn (B*T, C) bf16 (two-pass tiles)
//   blocks [512, 1536): wq|wk|wv -> wqkv[512][1536], wo -> bf16, biases pack
// ===========================================================================
__global__ void ln_cvt(const float* __restrict__ x, const float* __restrict__ gamma,
                       const float* __restrict__ beta, __nv_bfloat16* __restrict__ hn,
                       const float* __restrict__ wq, const float* __restrict__ wk,
                       const float* __restrict__ wv, const float* __restrict__ wo,
                       const float* __restrict__ bq, const float* __restrict__ bk,
                       const float* __restrict__ bv,
                       __nv_bfloat16* __restrict__ wqkv, __nv_bfloat16* __restrict__ wob,
                       float* __restrict__ bqkv) {
    int bid = blockIdx.x;
    int tid = threadIdx.x;
    if (bid >= 512) {
        // ---- weight convert/pack part ----
        int t = (bid - 512) * 256 + tid;
        int i = t * 4;                       // over 4*512*512 = 1M floats
        int w = i >> 18;
        int r = i & 0x3FFFF;
        const float* src = (w == 0) ? wq : (w == 1) ? wk : (w == 2) ? wv : wo;
        float4 v = *(const float4*)(src + r);
        uint2 p = {pk(v.x, v.y), pk(v.z, v.w)};
        if (w < 3) {
            int kk = r >> 9, n = r & 511;
            *(uint2*)(wqkv + (size_t)kk * 1536 + w * 512 + n) = p;
        } else {
            *(uint2*)(wob + r) = p;
        }
        if (t < 3 * DF)
            bqkv[t] = (t < 512) ? bq[t] : (t < 1024) ? bk[t - 512] : bv[t - 1024];
        return;
    }
    // ---- LayerNorm part ----
    int b = bid >> 6, t0 = (bid & 63) * 32;
    int tx = tid & 31, cy = tid >> 5;   // 8 c-lanes
    const float* xp = x + (size_t)b * CIN * SEQT + t0;
    float s = 0.f, s2 = 0.f;
#pragma unroll 8
    for (int c = cy; c < CIN; c += 8) {
        float v = xp[(size_t)c * SEQT + tx];
        s += v; s2 += v * v;
    }
    __shared__ float ss[8][32], ss2[8][32], mean_s[32], rstd_s[32];
    ss[cy][tx] = s; ss2[cy][tx] = s2;
    __syncthreads();
    if (cy == 0) {
        float S = 0.f, S2 = 0.f;
#pragma unroll
        for (int i = 0; i < 8; i++) { S += ss[i][tx]; S2 += ss2[i][tx]; }
        float mean = S * (1.f / CIN);
        float var = S2 * (1.f / CIN) - mean * mean;
        mean_s[tx] = mean;
        rstd_s[tx] = rsqrtf(var + 1e-5f);
    }
    __syncthreads();
    float mean = mean_s[tx], rstd = rstd_s[tx];
    __shared__ float tile[32][33];
    for (int c0 = 0; c0 < CIN; c0 += 32) {
#pragma unroll
        for (int j = 0; j < 4; j++) {
            int c = c0 + cy + j * 8;
            tile[cy + j * 8][tx] = (xp[(size_t)c * SEQT + tx] - mean) * rstd * gamma[c] + beta[c];
        }
        __syncthreads();
#pragma unroll
        for (int j = 0; j < 4; j++) {
            int t = cy + j * 8;
            hn[(size_t)(b * SEQT + t0 + t) * CIN + c0 + tx] = __float2bfloat16(tile[tx][t]);
        }
        __syncthreads();
    }
}

// ===========================================================================
// fused QKV GEMM: qkv[M,1536] = hn[M,512] @ wqkv[512,1536] + bqkv
// 128x128 tile, BK=64, 256 thr. 3-stage cp.async, ONE barrier per k-tile.
// Epilogue staged through smem for fully coalesced 16B global stores.
// ===========================================================================
#define GA_SZ 16384
#define GB_SZ 16384
#define GBUF  (GA_SZ + GB_SZ)
#define GEMM_SMEM (3 * GBUF)   // 98304
#define CST 68                  // staging row stride in 32-bit words (conflict-free)

__global__ __launch_bounds__(256, 2)
void gemm_qkv(const __nv_bfloat16* __restrict__ A, const __nv_bfloat16* __restrict__ W,
              const float* __restrict__ bias, __nv_bfloat16* __restrict__ C) {
    extern __shared__ char sm[];
    uint32_t sb = smem_u32(sm);
    const int tid = threadIdx.x;
    const int wid = tid >> 5, lane = tid & 31;
    const int g = lane >> 2, tg = lane & 3;
    const int bm = blockIdx.y * 128, bn = blockIdx.x * 128;
    const int wm = (wid & 3) * 32, wn = (wid >> 2) * 64;
    const float scale = (bn < 512) ? 0.125f * 1.44269504088896f : 1.0f;

#define G_ISSUE(kt, buf) do {                                                        \
        uint32_t base_ = sb + (uint32_t)(buf) * GBUF;                                \
        _Pragma("unroll")                                                            \
        for (int i_ = 0; i_ < 4; i_++) {                                             \
            int idx = tid + i_ * 256;                                                \
            int r = idx >> 3, c = idx & 7;                                           \
            cp16(base_ + r * 128 + ((c ^ (r & 7)) << 4),                             \
                 A + (size_t)(bm + r) * 512 + (kt) * 64 + c * 8);                    \
        }                                                                            \
        _Pragma("unroll")                                                            \
        for (int i_ = 0; i_ < 4; i_++) {                                             \
            int idx = tid + i_ * 256;                                                \
            int r = idx >> 4, c = idx & 15;                                          \
            cp16(base_ + GA_SZ + r * 256 + ((c ^ (r & 7)) << 4),                     \
                 W + (size_t)((kt) * 64 + r) * 1536 + bn + c * 8);                   \
        }                                                                            \
        CP_COMMIT();                                                                 \
    } while (0)

    float acc[2][8][4];
#pragma unroll
    for (int mt = 0; mt < 2; mt++)
#pragma unroll
        for (int nt = 0; nt < 8; nt++)
#pragma unroll
            for (int j = 0; j < 4; j++) acc[mt][nt][j] = 0.f;

    G_ISSUE(0, 0);
    G_ISSUE(1, 1);
    int br = 0;
    for (int kt = 0; kt < 8; kt++) {
        if (kt < 7) CP_WAIT1(); else CP_WAIT0();
        __syncthreads();
        if (kt + 2 < 8) {
            int bi = br + 2; if (bi >= 3) bi -= 3;
            G_ISSUE(kt + 2, bi);
        }
        uint32_t base = sb + br * GBUF;
#pragma unroll
        for (int ks = 0; ks < 4; ks++) {
            uint32_t a[2][4];
#pragma unroll
            for (int mt = 0; mt < 2; mt++) {
                int row = wm + mt * 16 + (lane & 7) + ((lane & 8) ? 8 : 0);
                int c = ks * 2 + ((lane >> 4) & 1);
                ldsm4(a[mt], base + row * 128 + ((c ^ (row & 7)) << 4));
            }
            uint32_t bb[4][4];
#pragma unroll
            for (int j = 0; j < 4; j++) {
                int krow = ks * 16 + (lane & 7) + ((lane & 8) ? 8 : 0);
                int c = ((wn + j * 16) >> 3) + ((lane >> 4) & 1);
                ldsm4t(bb[j], base + GA_SZ + krow * 256 + ((c ^ (krow & 7)) << 4));
            }
#pragma unroll
            for (int mt = 0; mt < 2; mt++)
#pragma unroll
                for (int j = 0; j < 4; j++) {
                    mma16(acc[mt][2 * j], a[mt], &bb[j][0]);
                    mma16(acc[mt][2 * j + 1], a[mt], &bb[j][2]);
                }
        }
        if (++br == 3) br = 0;
    }

    // epilogue: stage bf16 C tile in smem, then coalesced STG.128
    __syncthreads();
    uint32_t* cs = (uint32_t*)sm;
#pragma unroll
    for (int mt = 0; mt < 2; mt++) {
        int r0 = wm + mt * 16 + g;
#pragma unroll
        for (int nt = 0; nt < 8; nt++) {
            int col = wn + nt * 8 + 2 * tg;
            float b0 = bias[bn + col], b1 = bias[bn + col + 1];
            cs[r0 * CST + (col >> 1)] =
                pk((acc[mt][nt][0] + b0) * scale, (acc[mt][nt][1] + b1) * scale);
            cs[(r0 + 8) * CST + (col >> 1)] =
                pk((acc[mt][nt][2] + b0) * scale, (acc[mt][nt][3] + b1) * scale);
        }
    }
    __syncthreads();
    uint32_t* Cw = (uint32_t*)C;
#pragma unroll
    for (int i = 0; i < 8; i++) {
        int f = tid + i * 256;          // 2048 16B-chunks: 128 rows x 16
        int r = f >> 4, c4 = (f & 15) << 2;
        uint4 v = *(uint4*)(cs + r * CST + c4);
        *(uint4*)(Cw + (size_t)(bm + r) * 768 + (bn >> 1) + c4) = v;
    }
#undef G_ISSUE
}

// ===========================================================================
// output GEMM + residual + transpose: out[b][c][t] = x[b][c][t] +
//   (ctx[b*T+t][:] @ wo)[c] + bo[c].  3-stage, one barrier per k-tile.
// Epilogue staged through smem transposed [c][t]: coalesced LDG/STG along t.
// ===========================================================================
#define OST 132   // fp32 staging stride (words): conflict-free, 16B-aligned rows

__global__ __launch_bounds__(256, 2)
void gemm_out(const __nv_bfloat16* __restrict__ A, const __nv_bfloat16* __restrict__ W,
              const float* __restrict__ bias, const float* __restrict__ x,
              float* __restrict__ out) {
    extern __shared__ char sm[];
    uint32_t sb = smem_u32(sm);
    const int tid = threadIdx.x;
    const int wid = tid >> 5, lane = tid & 31;
    const int g = lane >> 2, tg = lane & 3;
    const int bm = blockIdx.y * 128, bn = blockIdx.x * 128;
    const int wm = (wid & 3) * 32, wn = (wid >> 2) * 64;

#define G_ISSUE(kt, buf) do {                                                        \
        uint32_t base_ = sb + (uint32_t)(buf) * GBUF;                                \
        _Pragma("unroll")                                                            \
        for (int i_ = 0; i_ < 4; i_++) {                                             \
            int idx = tid + i_ * 256;                                                \
            int r = idx >> 3, c = idx & 7;                                           \
            cp16(base_ + r * 128 + ((c ^ (r & 7)) << 4),                             \
                 A + (size_t)(bm + r) * 512 + (kt) * 64 + c * 8);                    \
        }                                                                            \
        _Pragma("unroll")                                                            \
        for (int i_ = 0; i_ < 4; i_++) {                                             \
            int idx = tid + i_ * 256;                                                \
            int r = idx >> 4, c = idx & 15;                                          \
            cp16(base_ + GA_SZ + r * 256 + ((c ^ (r & 7)) << 4),                     \
                 W + (size_t)((kt) * 64 + r) * 512 + bn + c * 8);                    \
        }                                                                            \
        CP_COMMIT();                                                                 \
    } while (0)

    float acc[2][8][4];
#pragma unroll
    for (int mt = 0; mt < 2; mt++)
#pragma unroll
        for (int nt = 0; nt < 8; nt++)
#pragma unroll
            for (int j = 0; j < 4; j++) acc[mt][nt][j] = 0.f;

    G_ISSUE(0, 0);
    G_ISSUE(1, 1);
    int br = 0;
    for (int kt = 0; kt < 8; kt++) {
        if (kt < 7) CP_WAIT1(); else CP_WAIT0();
        __syncthreads();
        if (kt + 2 < 8) {
            int bi = br + 2; if (bi >= 3) bi -= 3;
            G_ISSUE(kt + 2, bi);
        }
        uint32_t base = sb + br * GBUF;
#pragma unroll
        for (int ks = 0; ks < 4; ks++) {
            uint32_t a[2][4];
#pragma unroll
            for (int mt = 0; mt < 2; mt++) {
                int row = wm + mt * 16 + (lane & 7) + ((lane & 8) ? 8 : 0);
                int c = ks * 2 + ((lane >> 4) & 1);
                ldsm4(a[mt], base + row * 128 + ((c ^ (row & 7)) << 4));
            }
            uint32_t bb[4][4];
#pragma unroll
            for (int j = 0; j < 4; j++) {
                int krow = ks * 16 + (lane & 7) + ((lane & 8) ? 8 : 0);
                int c = ((wn + j * 16) >> 3) + ((lane >> 4) & 1);
                ldsm4t(bb[j], base + GA_SZ + krow * 256 + ((c ^ (krow & 7)) << 4));
            }
#pragma unroll
            for (int mt = 0; mt < 2; mt++)
#pragma unroll
                for (int j = 0; j < 4; j++) {
                    mma16(acc[mt][2 * j], a[mt], &bb[j][0]);
                    mma16(acc[mt][2 * j + 1], a[mt], &bb[j][2]);
                }
        }
        if (++br == 3) br = 0;
    }

    // epilogue phase 1: stage (acc + bias) transposed [c_local][t_local]
    __syncthreads();
    float* cs = (float*)sm;
#pragma unroll
    for (int mt = 0; mt < 2; mt++) {
        int t_l = wm + mt * 16 + g;
#pragma unroll
        for (int nt = 0; nt < 8; nt++) {
            int c_l = wn + nt * 8 + 2 * tg;
            float b0 = bias[bn + c_l], b1 = bias[bn + c_l + 1];
            cs[c_l * OST + t_l]           = acc[mt][nt][0] + b0;
            cs[(c_l + 1) * OST + t_l]     = acc[mt][nt][1] + b1;
            cs[c_l * OST + t_l + 8]       = acc[mt][nt][2] + b0;
            cs[(c_l + 1) * OST + t_l + 8] = acc[mt][nt][3] + b1;
        }
    }
    __syncthreads();
    // epilogue phase 2: residual add + store, coalesced along t
    const int bI = bm >> 11, t0g = bm & 2047;
#pragma unroll
    for (int i = 0; i < 16; i++) {
        int f = tid + i * 256;                // 4096 chunks: 128 c x 32 chunks
        int c_l = f >> 5, ch = (f & 31) << 2;
        size_t gidx = ((size_t)(bI * 512 + bn + c_l)) * 2048 + t0g + ch;
        float4 xv = *(const float4*)(x + gidx);
        float4 v  = *(float4*)(cs + c_l * OST + ch);
        v.x += xv.x; v.y += xv.y; v.z += xv.z; v.w += xv.w;
        *(float4*)(out + gidx) = v;
    }
#undef G_ISSUE
}

// ===========================================================================
// Flash attention, causal, bf16 mma, qkv packed (row stride 1536).
// NO-MAX softmax, bf16x2 exp2, ones-MMA denominator. 3-stage KV pipeline.
// 1-D grid, GLOBAL heavy-first order (all qt=15 CTAs start in wave 1;
// the tail wave is all 2-tile CTAs — LPT scheduling).
// ===========================================================================
#define FQ_SZ 16384
#define FKV_SZ 16384
#define FLASH_SMEM (FQ_SZ + 3 * FKV_SZ)   // 65536
#define QKV_ST 1536

__global__ __launch_bounds__(256, 2)
void flash_bf16(const __nv_bfloat16* __restrict__ qkv, __nv_bfloat16* __restrict__ ctx) {
    extern __shared__ char sm[];
    uint32_t sb = smem_u32(sm);
    const int qt = 15 - (int)(blockIdx.x >> 6);   // global heavy-first
    const int bh = (int)(blockIdx.x & 63);
    const int b = bh >> 3, h = bh & 7;
    const int qb = qt * 128;
    const int tid = threadIdx.x, wid = tid >> 5, lane = tid & 31;
    const int g = lane >> 2, tg = lane & 3;
    const int rowbase = qb + wid * 16;
    const int ktmax = 2 * qt + 2;

    const __nv_bfloat16* qp  = qkv + (size_t)(b * SEQT + qb) * QKV_ST + h * 64;
    const __nv_bfloat16* kb0 = qkv + (size_t)b * SEQT * QKV_ST + 512 + h * 64;
    const __nv_bfloat16* vb0 = qkv + (size_t)b * SEQT * QKV_ST + 1024 + h * 64;

#define F_ISSUE(kt, buf) do {                                                        \
        uint32_t base_ = sb + FQ_SZ + (uint32_t)(buf) * FKV_SZ;                      \
        const __nv_bfloat16* kp_ = kb0 + (size_t)(kt) * 64 * QKV_ST;                 \
        const __nv_bfloat16* vp_ = vb0 + (size_t)(kt) * 64 * QKV_ST;                 \
        _Pragma("unroll")                                                            \
        for (int i_ = 0; i_ < 2; i_++) {                                             \
            int idx = tid + i_ * 256;                                                \
            int r = idx >> 3, c = idx & 7;                                           \
            uint32_t off = r * 128 + ((c ^ (r & 7)) << 4);                           \
            cp16(base_ + off, kp_ + (size_t)r * QKV_ST + c * 8);                     \
            cp16(base_ + 8192 + off, vp_ + (size_t)r * QKV_ST + c * 8);              \
        }                                                                            \
        CP_COMMIT();                                                                 \
    } while (0)

    // group 0: Q + KV(0); group 1: KV(1)
#pragma unroll
    for (int i = 0; i < 4; i++) {
        int idx = tid + i * 256;
        int r = idx >> 3, c = idx & 7;
        cp16(sb + r * 128 + ((c ^ (r & 7)) << 4), qp + (size_t)r * QKV_ST + c * 8);
    }
    {
        uint32_t base_ = sb + FQ_SZ;
#pragma unroll
        for (int i = 0; i < 2; i++) {
            int idx = tid + i * 256;
            int r = idx >> 3, c = idx & 7;
            uint32_t off = r * 128 + ((c ^ (r & 7)) << 4);
            cp16(base_ + off, kb0 + (size_t)r * QKV_ST + c * 8);
            cp16(base_ + 8192 + off, vb0 + (size_t)r * QKV_ST + c * 8);
        }
        CP_COMMIT();
    }
    if (ktmax > 1) F_ISSUE(1, 1);

    float o[8][4];
#pragma unroll
    for (int nt = 0; nt < 8; nt++)
#pragma unroll
        for (int j = 0; j < 4; j++) o[nt][j] = 0.f;
    float lacc[4] = {0.f, 0.f, 0.f, 0.f};   // denominator via ones-MMA
    const uint32_t onesb[2] = {0x3F803F80u, 0x3F803F80u};   // bf16 1.0 x4
    uint32_t aq[4][4];

    int br = 0;
    for (int kt = 0; kt < ktmax; kt++) {
        if (kt + 1 < ktmax) CP_WAIT1(); else CP_WAIT0();
        __syncthreads();
        if (kt + 2 < ktmax) {
            int bi = br + 2; if (bi >= 3) bi -= 3;
            F_ISSUE(kt + 2, bi);
        }
        if (kt == 0) {
#pragma unroll
            for (int ks = 0; ks < 4; ks++) {
                int row = wid * 16 + (lane & 7) + ((lane & 8) ? 8 : 0);
                int c = ks * 2 + ((lane >> 4) & 1);
                ldsm4(aq[ks], sb + row * 128 + ((c ^ (row & 7)) << 4));
            }
        }
        if (kt * 64 <= rowbase + 15) {
            uint32_t base = sb + FQ_SZ + (uint32_t)br * FKV_SZ;
            float S[8][4];
#pragma unroll
            for (int nt = 0; nt < 8; nt++)
#pragma unroll
                for (int j = 0; j < 4; j++) S[nt][j] = 0.f;

            // S = Q K^T (log2-domain scale folded into Q)
#pragma unroll
            for (int ks = 0; ks < 4; ks++) {
#pragma unroll
                for (int j = 0; j < 4; j++) {
                    uint32_t kbf[4];
                    int krow = j * 16 + (lane & 7) + ((lane & 16) ? 8 : 0);
                    int c = ks * 2 + ((lane >> 3) & 1);
                    ldsm4(kbf, base + krow * 128 + ((c ^ (krow & 7)) << 4));
                    mma16(S[2 * j], aq[ks], &kbf[0]);
                    mma16(S[2 * j + 1], aq[ks], &kbf[2]);
                }
            }

            // causal mask (diagonal tiles only): ex2(bf16(-1e30)) == 0
            if (kt * 64 + 63 > rowbase) {
#pragma unroll
                for (int nt = 0; nt < 8; nt++)
#pragma unroll
                    for (int j = 0; j < 4; j++) {
                        int col = kt * 64 + nt * 8 + 2 * tg + (j & 1);
                        int row = rowbase + g + ((j >> 1) << 3);
                        if (col > row) S[nt][j] = -1e30f;
                    }
            }

            // P = exp2(S) in bf16x2; l accumulated by ones-MMA.
#pragma unroll
            for (int ksp = 0; ksp < 4; ksp++) {
                uint32_t ap[4] = {
                    ex2b(pk(S[2 * ksp][0], S[2 * ksp][1])),
                    ex2b(pk(S[2 * ksp][2], S[2 * ksp][3])),
                    ex2b(pk(S[2 * ksp + 1][0], S[2 * ksp + 1][1])),
                    ex2b(pk(S[2 * ksp + 1][2], S[2 * ksp + 1][3]))};
                mma16(lacc, ap, onesb);   // l += P @ 1
#pragma unroll
                for (int j = 0; j < 4; j++) {
                    uint32_t vbf[4];
                    int krow = ksp * 16 + (lane & 7) + ((lane & 8) ? 8 : 0);
                    int c = j * 2 + ((lane >> 4) & 1);
                    ldsm4t(vbf, base + 8192 + krow * 128 + ((c ^ (krow & 7)) << 4));
                    mma16(o[2 * j], ap, &vbf[0]);
                    mma16(o[2 * j + 1], ap, &vbf[2]);
                }
            }
        }
        if (++br == 3) br = 0;
    }

    // every lane already holds the full row sums (ones-MMA) — no shuffles
    float inv0 = 1.f / lacc[0], inv1 = 1.f / lacc[2];
    uint32_t* c0p = (uint32_t*)(ctx + (size_t)(b * SEQT + rowbase + g) * 512 + h * 64);
    uint32_t* c1p = (uint32_t*)(ctx + (size_t)(b * SEQT + rowbase + g + 8) * 512 + h * 64);
#pragma unroll
    for (int nt = 0; nt < 8; nt++) {
        int cw = (nt * 8 + 2 * tg) >> 1;
        c0p[cw] = pk(o[nt][0] * inv0, o[nt][1] * inv0);
        c1p[cw] = pk(o[nt][2] * inv1, o[nt][3] * inv1);
    }
#undef F_ISSUE
}

// ===========================================================================
extern "C" void kernel_launch(void* const* d_in, const int* in_sizes, int n_in,
                              void* d_out, int out_size) {
    const float* x     = (const float*)d_in[0];
    const float* gamma = (const float*)d_in[1];
    const float* beta  = (const float*)d_in[2];
    const float* wq = (const float*)d_in[3];
    const float* bq = (const float*)d_in[4];
    const float* wk = (const float*)d_in[5];
    const float* bk = (const float*)d_in[6];
    const float* wv = (const float*)d_in[7];
    const float* bv = (const float*)d_in[8];
    const float* wo = (const float*)d_in[9];
    const float* bo = (const float*)d_in[10];
    float* out = (float*)d_out;

    __nv_bfloat16 *hn, *qkv, *cb, *wqkv, *wob;
    float *bqkv;
    cudaGetSymbolAddress((void**)&hn,   g_hn);
    cudaGetSymbolAddress((void**)&qkv,  g_qkv);
    cudaGetSymbolAddress((void**)&cb,   g_ctx);
    cudaGetSymbolAddress((void**)&wqkv, g_wqkv);
    cudaGetSymbolAddress((void**)&wob,  g_wo);
    cudaGetSymbolAddress((void**)&bqkv, g_bqkv);

    ln_cvt<<<1536, 256>>>(x, gamma, beta, hn, wq, wk, wv, wo, bq, bk, bv,
                          wqkv, wob, bqkv);

    cudaFuncSetAttribute(gemm_qkv, cudaFuncAttributeMaxDynamicSharedMemorySize, GEMM_SMEM);
    cudaFuncSetAttribute(gemm_out, cudaFuncAttributeMaxDynamicSharedMemorySize, GEMM_SMEM);
    gemm_qkv<<<dim3(12, MROWS / 128), 256, GEMM_SMEM>>>(hn, wqkv, bqkv, qkv);

    cudaFuncSetAttribute(flash_bf16, cudaFuncAttributeMaxDynamicSharedMemorySize, FLASH_SMEM);
    flash_bf16<<<1024, 256, FLASH_SMEM>>>(qkv, cb);

    gemm_out<<<dim3(4, MROWS / 128), 256, GEMM_SMEM>>>(cb, wob, bo, x, out);
}